// round 1
// baseline (speedup 1.0000x reference)
#include <cuda_runtime.h>
#include <cuda_bf16.h>
#include <math.h>

#define N_TOK   8192
#define D_DIM   4096
#define N_EXP   64
#define TOP_K   2
#define CAP     160           // ceil(1.25*8192/64)
#define NEC     (N_TOK * N_EXP * CAP)        // 83,886,080
#define FLAT    (N_TOK * TOP_K)              // 16384

// ---------------- device scratch (no allocations allowed) ----------------
__device__ float g_gate_t[D_DIM * N_EXP];    // gate transposed [k][e]
__device__ int   g_top_idx[FLAT];
__device__ float g_top_w[FLAT];
__device__ int   g_slot[FLAT];
__device__ float g_psum[N_EXP];              // sum of probs per expert
__device__ int   g_cnt[N_EXP];               // assignment counts per expert

// ---------------- gate transpose: gate_w [E][D] -> g_gate_t [D][E] --------
__global__ void k_transpose_gate(const float* __restrict__ gate_w) {
    int idx = blockIdx.x * blockDim.x + threadIdx.x;   // grid covers D*E
    int k = idx >> 6;
    int e = idx & 63;
    g_gate_t[idx] = gate_w[(size_t)e * D_DIM + k];
}

__global__ void k_zero_psum() {
    g_psum[threadIdx.x] = 0.0f;
}

// ---------------- fused GEMM + softmax + top2 ----------------------------
// block: 256 threads, handles 32 tokens x 64 experts. grid = 256 blocks.
__global__ void __launch_bounds__(256)
k_gemm_topk(const float* __restrict__ x, float* __restrict__ probs_out) {
    __shared__ float xs[32][64];       // [token][k]
    __shared__ float gs[64][64];       // [k][expert]
    __shared__ float lg[32][65];       // logits, padded
    __shared__ float smax[32], sinv[32];
    __shared__ float spsum[N_EXP];

    const int tid = threadIdx.x;
    const int tx = tid & 15;           // expert group (4 experts)
    const int ty = tid >> 4;           // token pair group (2 tokens)
    const int n0 = blockIdx.x * 32;

    float acc[2][4];
#pragma unroll
    for (int i = 0; i < 2; i++)
#pragma unroll
        for (int j = 0; j < 4; j++) acc[i][j] = 0.0f;

    for (int kc = 0; kc < D_DIM; kc += 64) {
        // load x tile: 32 tokens x 64 k  (512 float4)
#pragma unroll
        for (int l = 0; l < 2; l++) {
            int idx = tid + l * 256;
            int t = idx >> 4, q = idx & 15;
            *(float4*)&xs[t][q * 4] =
                *(const float4*)&x[(size_t)(n0 + t) * D_DIM + kc + q * 4];
        }
        // load gate tile: 64 k x 64 e (1024 float4), already transposed
#pragma unroll
        for (int l = 0; l < 4; l++) {
            int idx = tid + l * 256;
            int kk = idx >> 4, q = idx & 15;
            *(float4*)&gs[kk][q * 4] =
                *(const float4*)&g_gate_t[(size_t)(kc + kk) * N_EXP + q * 4];
        }
        __syncthreads();

#pragma unroll 16
        for (int kk = 0; kk < 64; kk++) {
            float a0 = xs[2 * ty][kk];
            float a1 = xs[2 * ty + 1][kk];
            float4 g = *(float4*)&gs[kk][tx * 4];
            acc[0][0] += a0 * g.x; acc[0][1] += a0 * g.y;
            acc[0][2] += a0 * g.z; acc[0][3] += a0 * g.w;
            acc[1][0] += a1 * g.x; acc[1][1] += a1 * g.y;
            acc[1][2] += a1 * g.z; acc[1][3] += a1 * g.w;
        }
        __syncthreads();
    }

    // stage logits into shared
#pragma unroll
    for (int j = 0; j < 4; j++) {
        lg[2 * ty][tx * 4 + j]     = acc[0][j];
        lg[2 * ty + 1][tx * 4 + j] = acc[1][j];
    }
    if (tid < N_EXP) spsum[tid] = 0.0f;
    __syncthreads();

    // per-token softmax stats + top-2 (exact fp32 logits -> exact selection)
    if (tid < 32) {
        const int t = tid;
        float m = -INFINITY;
#pragma unroll
        for (int e = 0; e < N_EXP; e++) m = fmaxf(m, lg[t][e]);
        float s = 0.0f;
#pragma unroll
        for (int e = 0; e < N_EXP; e++) s += expf(lg[t][e] - m);
        float inv = 1.0f / s;
        smax[t] = m;
        sinv[t] = inv;

        float v1 = -INFINITY, v2 = -INFINITY;
        int i1 = 0, i2 = 0;
#pragma unroll
        for (int e = 0; e < N_EXP; e++) {
            float v = lg[t][e];
            if (v > v1) { v2 = v1; i2 = i1; v1 = v; i1 = e; }
            else if (v > v2) { v2 = v; i2 = e; }
        }
        float p1 = expf(v1 - m) * inv;
        float p2 = expf(v2 - m) * inv;
        float r = 1.0f / (p1 + p2);
        int n = n0 + t;
        g_top_idx[2 * n]     = i1;
        g_top_idx[2 * n + 1] = i2;
        g_top_w[2 * n]       = p1 * r;
        g_top_w[2 * n + 1]   = p2 * r;
    }
    __syncthreads();

    // write probs (2048 floats) + per-expert prob sums
    {
        int t  = tid >> 3;
        int e0 = (tid & 7) * 8;
        float m = smax[t], inv = sinv[t];
        float buf[8];
#pragma unroll
        for (int i = 0; i < 8; i++) {
            float p = expf(lg[t][e0 + i] - m) * inv;
            buf[i] = p;
            atomicAdd(&spsum[e0 + i], p);
        }
        float4* dst = (float4*)&probs_out[(size_t)(n0 + t) * N_EXP + e0];
        dst[0] = make_float4(buf[0], buf[1], buf[2], buf[3]);
        dst[1] = make_float4(buf[4], buf[5], buf[6], buf[7]);
    }
    __syncthreads();
    if (tid < N_EXP) atomicAdd(&g_psum[tid], spsum[tid]);
}

// ---------------- per-expert exclusive scan of assignments ----------------
// one block per expert; 256 threads; FLAT=16384 -> 64 entries per thread
__global__ void __launch_bounds__(256)
k_scan(void) {
    __shared__ int ss[256];
    const int e = blockIdx.x;
    const int tid = threadIdx.x;
    const int base = tid * 64;

    int local = 0;
#pragma unroll 8
    for (int j = 0; j < 64; j++) local += (g_top_idx[base + j] == e);

    ss[tid] = local;
    __syncthreads();
    // Hillis-Steele inclusive scan over 256
    for (int off = 1; off < 256; off <<= 1) {
        int t = (tid >= off) ? ss[tid - off] : 0;
        __syncthreads();
        ss[tid] += t;
        __syncthreads();
    }
    int excl = ss[tid] - local;

    int c = excl;
#pragma unroll 8
    for (int j = 0; j < 64; j++) {
        if (g_top_idx[base + j] == e) { g_slot[base + j] = c; c++; }
    }
    if (tid == 255) g_cnt[e] = ss[255];
}

// ---------------- scatter the 16384 nonzeros ------------------------------
__global__ void k_scatter(float* __restrict__ out_mask,
                          float* __restrict__ out_comb) {
    int i = blockIdx.x * blockDim.x + threadIdx.x;   // 0..FLAT-1
    if (i >= FLAT) return;
    int e = g_top_idx[i];
    int s = g_slot[i];
    if (s < CAP) {
        int n = i >> 1;
        size_t off = (size_t)n * (N_EXP * CAP) + (size_t)e * CAP + s;
        out_mask[off] = 1.0f;
        out_comb[off] = g_top_w[i];
    }
}

// ---------------- load-balancing loss -------------------------------------
__global__ void k_loss(float* __restrict__ out_loss) {
    __shared__ float sh[64];
    int e = threadIdx.x;
    float f = (float)g_cnt[e] / (float)FLAT;
    float p = g_psum[e] / (float)N_TOK;
    sh[e] = f * p;
    __syncthreads();
    for (int off = 32; off > 0; off >>= 1) {
        if (e < off) sh[e] += sh[e + off];
        __syncthreads();
    }
    if (e == 0) out_loss[0] = 0.01f * (float)N_EXP * sh[0];
}

// ---------------- launch ---------------------------------------------------
extern "C" void kernel_launch(void* const* d_in, const int* in_sizes, int n_in,
                              void* d_out, int out_size) {
    const float* x      = (const float*)d_in[0];
    const float* gate_w = (const float*)d_in[1];
    float* out = (float*)d_out;

    float* out_mask  = out;                                  // N*E*C
    float* out_comb  = out + (size_t)NEC;                    // N*E*C
    float* out_probs = out + (size_t)2 * NEC;                // N*E
    float* out_loss  = out + (size_t)2 * NEC + (size_t)N_TOK * N_EXP;

    // zero the sparse outputs (mask + combine)
    cudaMemsetAsync(out, 0, (size_t)2 * NEC * sizeof(float));

    k_transpose_gate<<<(D_DIM * N_EXP) / 256, 256>>>(gate_w);
    k_zero_psum<<<1, 64>>>();
    k_gemm_topk<<<N_TOK / 32, 256>>>(x, out_probs);
    k_scan<<<N_EXP, 256>>>();
    k_scatter<<<FLAT / 256, 256>>>(out_mask, out_comb);
    k_loss<<<1, 64>>>(out_loss);
}